// round 2
// baseline (speedup 1.0000x reference)
#include <cuda_runtime.h>

// Shapes fixed by the problem: x,f = (B=2, 3, T=5, H=720, W=1280) fp32.
// Output = concat(ow, xw), each (B,3,T,H,W) fp32.
constexpr unsigned B  = 2;
constexpr unsigned C  = 3;
constexpr unsigned T  = 5;
constexpr unsigned H  = 720;
constexpr unsigned W  = 1280;
constexpr unsigned PLANE = H * W;            // 921,600
constexpr unsigned CH    = T * PLANE;        // 4,608,000 (stride between channels)
constexpr unsigned HALF  = B * C * CH;       // 27,648,000 (one output tensor)
constexpr unsigned NPIX  = B * T * PLANE;    // 9,216,000
constexpr unsigned NQUAD = NPIX / 4;         // 2,304,000 (W divisible by 4)
constexpr unsigned ROWQ  = W / 4;            // 320 float4 per row

__global__ __launch_bounds__(256)
void ImageBWarp_65343632441725_kernel(const float* __restrict__ x,
                                      const float* __restrict__ f,
                                      float* __restrict__ out)
{
    unsigned idx4 = blockIdx.x * 256u + threadIdx.x;
    if (idx4 >= NQUAD) return;

    unsigned row = idx4 / ROWQ;              // [0, B*T*H)
    unsigned wq  = idx4 - row * ROWQ;
    unsigned w0  = wq * 4u;
    unsigned h   = row % H;
    unsigned bt  = row / H;                  // [0, B*T)
    unsigned b   = bt / T;
    unsigned t   = bt - b * T;

    unsigned hw   = h * W + w0;              // 16B-aligned (w0 % 4 == 0)
    unsigned base = (b * (C * T) + t) * PLANE;

    // flow + weight logit: three coalesced float4 loads
    const float4 fx4 = *(const float4*)(f + base + hw);
    const float4 fy4 = *(const float4*)(f + base + CH + hw);
    const float4 wl4 = *(const float4*)(f + base + 2u * CH + hw);

    float fx[4] = {fx4.x, fx4.y, fx4.z, fx4.w};
    float fy[4] = {fy4.x, fy4.y, fy4.z, fy4.w};
    float wl[4] = {wl4.x, wl4.y, wl4.z, wl4.w};

    float m00[4], m10[4], m01[4], m11[4];
    unsigned o00[4], o10[4], o01[4], o11[4];
    float wgt[4], owv[4];

#pragma unroll
    for (int j = 0; j < 4; j++) {
        float gx = (float)(w0 + j) + fx[j];
        float gy = (float)h + fy[j];

        float x0f = floorf(gx);
        float y0f = floorf(gy);
        float wx1 = gx - x0f;
        float wy1 = gy - y0f;
        float wx0 = 1.0f - wx1;
        float wy0 = 1.0f - wy1;

        int ix0 = (int)x0f;
        int iy0 = (int)y0f;
        int ix1 = ix0 + 1;
        int iy1 = iy0 + 1;

        bool vx0 = (unsigned)ix0 < W;
        bool vx1 = (unsigned)ix1 < W;
        bool vy0 = (unsigned)iy0 < H;
        bool vy1 = (unsigned)iy1 < H;

        m00[j] = (vx0 && vy0) ? wx0 * wy0 : 0.0f;
        m10[j] = (vx1 && vy0) ? wx1 * wy0 : 0.0f;
        m01[j] = (vx0 && vy1) ? wx0 * wy1 : 0.0f;
        m11[j] = (vx1 && vy1) ? wx1 * wy1 : 0.0f;

        unsigned cx0 = (unsigned)min(max(ix0, 0), (int)W - 1);
        unsigned cx1 = (unsigned)min(max(ix1, 0), (int)W - 1);
        unsigned cy0 = (unsigned)min(max(iy0, 0), (int)H - 1);
        unsigned cy1 = (unsigned)min(max(iy1, 0), (int)H - 1);

        o00[j] = cy0 * W + cx0;
        o10[j] = cy0 * W + cx1;
        o01[j] = cy1 * W + cx0;
        o11[j] = cy1 * W + cx1;

        wgt[j] = 1.0f / (1.0f + __expf(-wl[j]));
        owv[j] = wgt[j] * (m00[j] + m10[j] + m01[j] + m11[j]);
    }

    float4 ow4 = make_float4(owv[0], owv[1], owv[2], owv[3]);

    float*       out_ow = out + base + hw;
    float*       out_xw = out_ow + HALF;
    const float* xb     = x + base;

#pragma unroll
    for (unsigned c = 0; c < C; c++) {
        const float* xc = xb + c * CH;
        float s[4];
#pragma unroll
        for (int j = 0; j < 4; j++) {
            s[j] = m00[j] * __ldg(xc + o00[j])
                 + m10[j] * __ldg(xc + o10[j])
                 + m01[j] * __ldg(xc + o01[j])
                 + m11[j] * __ldg(xc + o11[j]);
            s[j] *= wgt[j];
        }
        *(float4*)(out_ow + c * CH) = ow4;
        *(float4*)(out_xw + c * CH) = make_float4(s[0], s[1], s[2], s[3]);
    }
}

extern "C" void kernel_launch(void* const* d_in, const int* in_sizes, int n_in,
                              void* d_out, int out_size)
{
    const float* x = (const float*)d_in[0];
    const float* f = (const float*)d_in[1];
    float* out = (float*)d_out;

    const unsigned threads = 256;
    const unsigned blocks  = (NQUAD + threads - 1) / threads;  // 9000
    ImageBWarp_65343632441725_kernel<<<blocks, threads>>>(x, f, out);
}

// round 3
// speedup vs baseline: 1.2778x; 1.2778x over previous
#include <cuda_runtime.h>

// Shapes fixed by the problem: x,f = (B=2, 3, T=5, H=720, W=1280) fp32.
// Output = concat(ow, xw), each (B,3,T,H,W) fp32.
constexpr unsigned B  = 2;
constexpr unsigned C  = 3;
constexpr unsigned T  = 5;
constexpr unsigned H  = 720;
constexpr unsigned W  = 1280;
constexpr unsigned PLANE = H * W;            // 921,600
constexpr unsigned CH    = T * PLANE;        // 4,608,000
constexpr unsigned HALF  = B * C * CH;       // 27,648,000
constexpr unsigned NPIX  = B * T * PLANE;    // 9,216,000
constexpr unsigned NPAIR = NPIX / 2;         // 4,608,000 (W divisible by 2)
constexpr unsigned ROWP  = W / 2;            // 640 float2 per row

__global__ __launch_bounds__(256, 5)        // cap regs ~48 -> ~40 warps/SM
void ImageBWarp_65343632441725_kernel(const float* __restrict__ x,
                                      const float* __restrict__ f,
                                      float* __restrict__ out)
{
    unsigned idx2 = blockIdx.x * 256u + threadIdx.x;
    if (idx2 >= NPAIR) return;

    unsigned row = idx2 / ROWP;              // [0, B*T*H)
    unsigned wp  = idx2 - row * ROWP;
    unsigned w0  = wp * 2u;
    unsigned h   = row % H;
    unsigned bt  = row / H;                  // [0, B*T)
    unsigned b   = bt / T;
    unsigned t   = bt - b * T;

    unsigned hw   = h * W + w0;              // 8B-aligned
    unsigned base = (b * (C * T) + t) * PLANE;

    // flow + weight logit: three coalesced float2 loads
    const float2 fx2 = *(const float2*)(f + base + hw);
    const float2 fy2 = *(const float2*)(f + base + CH + hw);
    const float2 wl2 = *(const float2*)(f + base + 2u * CH + hw);

    float fx[2] = {fx2.x, fx2.y};
    float fy[2] = {fy2.x, fy2.y};
    float wl[2] = {wl2.x, wl2.y};

    float m00[2], m10[2], m01[2], m11[2];
    unsigned o00[2], o10[2], o01[2], o11[2];
    float wgt[2];
    float owv[2];

#pragma unroll
    for (int j = 0; j < 2; j++) {
        float gx = (float)(w0 + j) + fx[j];
        float gy = (float)h + fy[j];

        float x0f = floorf(gx);
        float y0f = floorf(gy);
        float wx1 = gx - x0f;
        float wy1 = gy - y0f;
        float wx0 = 1.0f - wx1;
        float wy0 = 1.0f - wy1;

        int ix0 = (int)x0f;
        int iy0 = (int)y0f;
        int ix1 = ix0 + 1;
        int iy1 = iy0 + 1;

        bool vx0 = (unsigned)ix0 < W;
        bool vx1 = (unsigned)ix1 < W;
        bool vy0 = (unsigned)iy0 < H;
        bool vy1 = (unsigned)iy1 < H;

        m00[j] = (vx0 && vy0) ? wx0 * wy0 : 0.0f;
        m10[j] = (vx1 && vy0) ? wx1 * wy0 : 0.0f;
        m01[j] = (vx0 && vy1) ? wx0 * wy1 : 0.0f;
        m11[j] = (vx1 && vy1) ? wx1 * wy1 : 0.0f;

        unsigned cx0 = (unsigned)min(max(ix0, 0), (int)W - 1);
        unsigned cx1 = (unsigned)min(max(ix1, 0), (int)W - 1);
        unsigned cy0 = (unsigned)min(max(iy0, 0), (int)H - 1);
        unsigned cy1 = (unsigned)min(max(iy1, 0), (int)H - 1);

        o00[j] = cy0 * W + cx0;
        o10[j] = cy0 * W + cx1;
        o01[j] = cy1 * W + cx0;
        o11[j] = cy1 * W + cx1;

        wgt[j] = __fdividef(1.0f, 1.0f + __expf(-wl[j]));
        owv[j] = wgt[j] * (m00[j] + m10[j] + m01[j] + m11[j]);
    }

    float2 ow2 = make_float2(owv[0], owv[1]);

    float*       out_ow = out + base + hw;
    float*       out_xw = out_ow + HALF;
    const float* xb     = x + base;

#pragma unroll
    for (unsigned c = 0; c < C; c++) {
        const float* xc = xb + c * CH;
        // batch all 8 gathers for this channel, then reduce
        float v00a = __ldg(xc + o00[0]);
        float v10a = __ldg(xc + o10[0]);
        float v01a = __ldg(xc + o01[0]);
        float v11a = __ldg(xc + o11[0]);
        float v00b = __ldg(xc + o00[1]);
        float v10b = __ldg(xc + o10[1]);
        float v01b = __ldg(xc + o01[1]);
        float v11b = __ldg(xc + o11[1]);

        float sa = m00[0] * v00a + m10[0] * v10a + m01[0] * v01a + m11[0] * v11a;
        float sb = m00[1] * v00b + m10[1] * v10b + m01[1] * v01b + m11[1] * v11b;

        *(float2*)(out_ow + c * CH) = ow2;
        *(float2*)(out_xw + c * CH) = make_float2(sa * wgt[0], sb * wgt[1]);
    }
}

extern "C" void kernel_launch(void* const* d_in, const int* in_sizes, int n_in,
                              void* d_out, int out_size)
{
    const float* x = (const float*)d_in[0];
    const float* f = (const float*)d_in[1];
    float* out = (float*)d_out;

    const unsigned threads = 256;
    const unsigned blocks  = (NPAIR + threads - 1) / threads;  // 18000
    ImageBWarp_65343632441725_kernel<<<blocks, threads>>>(x, f, out);
}